// round 12
// baseline (speedup 1.0000x reference)
#include <cuda_runtime.h>
#include <math.h>

// ---------------------------------------------------------------------------
// CameraEstimator: camera[b] = sum_c x[b,c,:,:] * W[c]  (B=32768, C=256)
// then R[b] = nearest special-orthogonal matrix to camera[b].
//
// Fused single kernel, cp.async.bulk pipeline: grid=2048 blocks, each streams
// 16 b-tiles through a 3-stage SMEM ring filled by cp.async.bulk (TMA path —
// no LDG/STS L1tex traffic, no per-iteration __syncthreads). 9 warps -> 9
// outputs via conflict-free stride-9 LDS + shuffle reduce; mbarrier
// full/empty pairs provide the producer/consumer sync. 16-thread tail solves
// the 3x3 Procrustes problems.
//
// R = u1 v1^T + u2 v2^T + (u1 x u2)(v1 x v2)^T with v1,v2 top eigenvectors
// of M^T M, u_i = GS-normalized M v_i == reference u_flip @ vh.
// ---------------------------------------------------------------------------

#define MAXB 65536
__device__ float g_cam[MAXB * 9];   // fallback path only

// ---------------- tiny PTX helpers ------------------------------------------
static __device__ __forceinline__ unsigned smem_u32(const void* p) {
    unsigned a;
    asm("{ .reg .u64 t; cvta.to.shared.u64 t, %1; cvt.u32.u64 %0, t; }"
        : "=r"(a) : "l"(p));
    return a;
}
static __device__ __forceinline__ void mbar_init(unsigned a, unsigned cnt) {
    asm volatile("mbarrier.init.shared.b64 [%0], %1;" :: "r"(a), "r"(cnt) : "memory");
}
static __device__ __forceinline__ void mbar_arrive(unsigned a) {
    asm volatile("mbarrier.arrive.shared.b64 _, [%0];" :: "r"(a) : "memory");
}
static __device__ __forceinline__ void mbar_expect_tx(unsigned a, unsigned bytes) {
    asm volatile("mbarrier.arrive.expect_tx.shared.b64 _, [%0], %1;"
                 :: "r"(a), "r"(bytes) : "memory");
}
static __device__ __forceinline__ void mbar_wait(unsigned a, unsigned phase) {
    asm volatile(
        "{\n\t.reg .pred P;\n\t"
        "WL%=:\n\t"
        "mbarrier.try_wait.parity.acquire.cta.shared::cta.b64 P, [%0], %1, 0x989680;\n\t"
        "@P bra.uni WD%=;\n\t"
        "bra.uni WL%=;\n\t"
        "WD%=:\n\t}"
        :: "r"(a), "r"(phase) : "memory");
}
static __device__ __forceinline__ void bulk_g2s(unsigned dst, const void* src,
                                                unsigned bytes, unsigned mbar) {
    asm volatile(
        "cp.async.bulk.shared::cta.global.mbarrier::complete_tx::bytes [%0], [%1], %2, [%3];"
        :: "r"(dst), "l"(src), "r"(bytes), "r"(mbar) : "memory");
}

// ---------------- shared 3x3 Procrustes solve (fp32) ------------------------

__device__ __forceinline__ void bestNull(float a00, float a01, float a02,
                                         float a11, float a12, float a22,
                                         float lam, float& vx, float& vy, float& vz) {
    float b00 = a00 - lam, b11 = a11 - lam, b22 = a22 - lam;
    float c0x = a01 * a12 - a02 * b11;      // r0 x r1
    float c0y = a02 * a01 - b00 * a12;
    float c0z = b00 * b11 - a01 * a01;
    float c1x = a01 * b22 - a02 * a12;      // r0 x r2
    float c1y = a02 * a02 - b00 * b22;
    float c1z = b00 * a12 - a01 * a02;
    float c2x = b11 * b22 - a12 * a12;      // r1 x r2
    float c2y = a12 * a02 - a01 * b22;
    float c2z = a01 * a12 - b11 * a02;
    float n0 = c0x * c0x + c0y * c0y + c0z * c0z;
    float n1 = c1x * c1x + c1y * c1y + c1z * c1z;
    float n2 = c2x * c2x + c2y * c2y + c2z * c2z;
    float nx = c0x, ny = c0y, nz = c0z, nn = n0;
    if (n1 > nn) { nx = c1x; ny = c1y; nz = c1z; nn = n1; }
    if (n2 > nn) { nx = c2x; ny = c2y; nz = c2z; nn = n2; }
    if (nn < 1e-30f) { vx = 1.f; vy = 0.f; vz = 0.f; return; }
    float r = rsqrtf(nn);
    vx = nx * r; vy = ny * r; vz = nz * r;
}

__device__ __forceinline__ void perpOf(float vx, float vy, float vz,
                                       float& px, float& py, float& pz) {
    float ax = fabsf(vx), ay = fabsf(vy), az = fabsf(vz);
    float ex = 0.f, ey = 0.f, ez = 0.f;
    if (ax <= ay && ax <= az) ex = 1.f;
    else if (ay <= az)        ey = 1.f;
    else                      ez = 1.f;
    px = ey * vz - ez * vy;
    py = ez * vx - ex * vz;
    pz = ex * vy - ey * vx;
}

__device__ __forceinline__ void solve3x3(const float* __restrict__ m,
                                         float* __restrict__ o) {
    float m00 = m[0], m01 = m[1], m02 = m[2];
    float m10 = m[3], m11 = m[4], m12 = m[5];
    float m20 = m[6], m21 = m[7], m22 = m[8];

    float a00 = m00 * m00 + m10 * m10 + m20 * m20;
    float a01 = m00 * m01 + m10 * m11 + m20 * m21;
    float a02 = m00 * m02 + m10 * m12 + m20 * m22;
    float a11 = m01 * m01 + m11 * m11 + m21 * m21;
    float a12 = m01 * m02 + m11 * m12 + m21 * m22;
    float a22 = m02 * m02 + m12 * m12 + m22 * m22;

    float tr  = a00 + a11 + a22;
    float inv = (tr > 1e-30f) ? (1.0f / tr) : 0.f;
    a00 *= inv; a01 *= inv; a02 *= inv;
    a11 *= inv; a12 *= inv; a22 *= inv;

    float e2 = a00 * a11 + a00 * a22 + a11 * a22
             - a01 * a01 - a02 * a02 - a12 * a12;
    float dm = m00 * (m11 * m22 - m12 * m21)
             - m01 * (m10 * m22 - m12 * m20)
             + m02 * (m10 * m21 - m11 * m20);
    float e3 = (dm * dm) * (inv * inv * inv);

    float p2  = 1.0f - 3.0f * e2; if (p2 < 0.f) p2 = 0.f;
    float lam = (1.0f / 3.0f) + (2.0f / 3.0f) * sqrtf(p2);
#pragma unroll
    for (int it = 0; it < 8; ++it) {
        float f  = ((lam - 1.0f) * lam + e2) * lam - e3;
        float fp = (3.0f * lam - 2.0f) * lam + e2;
        lam -= f / (fp + 1e-30f);
    }
    float S = 1.0f - lam;
    float P = e2 - lam * S;
    float disc = S * S - 4.0f * P; if (disc < 0.f) disc = 0.f;
    float L2 = 0.5f * (S + sqrtf(disc));

    float v1x, v1y, v1z;
    bestNull(a00, a01, a02, a11, a12, a22, lam, v1x, v1y, v1z);

    float c2x, c2y, c2z;
    bestNull(a00, a01, a02, a11, a12, a22, L2, c2x, c2y, c2z);
    float dp = c2x * v1x + c2y * v1y + c2z * v1z;
    float v2x = c2x - dp * v1x, v2y = c2y - dp * v1y, v2z = c2z - dp * v1z;
    float n = v2x * v2x + v2y * v2y + v2z * v2z;
    if (n < 1e-12f) { perpOf(v1x, v1y, v1z, v2x, v2y, v2z);
                      n = v2x * v2x + v2y * v2y + v2z * v2z; }
    float rn = rsqrtf(n);
    v2x *= rn; v2y *= rn; v2z *= rn;
    float v3x = v1y * v2z - v1z * v2y;
    float v3y = v1z * v2x - v1x * v2z;
    float v3z = v1x * v2y - v1y * v2x;

    float u1x = m00 * v1x + m01 * v1y + m02 * v1z;
    float u1y = m10 * v1x + m11 * v1y + m12 * v1z;
    float u1z = m20 * v1x + m21 * v1y + m22 * v1z;
    n = u1x * u1x + u1y * u1y + u1z * u1z;
    if (n < 1e-30f) { u1x = 1.f; u1y = 0.f; u1z = 0.f; n = 1.f; }
    rn = rsqrtf(n); u1x *= rn; u1y *= rn; u1z *= rn;

    float t2x = m00 * v2x + m01 * v2y + m02 * v2z;
    float t2y = m10 * v2x + m11 * v2y + m12 * v2z;
    float t2z = m20 * v2x + m21 * v2y + m22 * v2z;
    dp = t2x * u1x + t2y * u1y + t2z * u1z;
    t2x -= dp * u1x; t2y -= dp * u1y; t2z -= dp * u1z;
    n = t2x * t2x + t2y * t2y + t2z * t2z;
    if (n < 1e-20f) { perpOf(u1x, u1y, u1z, t2x, t2y, t2z);
                      n = t2x * t2x + t2y * t2y + t2z * t2z; }
    rn = rsqrtf(n);
    float u2x = t2x * rn, u2y = t2y * rn, u2z = t2z * rn;
    float u3x = u1y * u2z - u1z * u2y;
    float u3y = u1z * u2x - u1x * u2z;
    float u3z = u1x * u2y - u1y * u2x;

    o[0] = u1x * v1x + u2x * v2x + u3x * v3x;
    o[1] = u1x * v1y + u2x * v2y + u3x * v3y;
    o[2] = u1x * v1z + u2x * v2z + u3x * v3z;
    o[3] = u1y * v1x + u2y * v2x + u3y * v3x;
    o[4] = u1y * v1y + u2y * v2y + u3y * v3y;
    o[5] = u1y * v1z + u2y * v2z + u3y * v3z;
    o[6] = u1z * v1x + u2z * v2x + u3z * v3x;
    o[7] = u1z * v1y + u2z * v2y + u3z * v3y;
    o[8] = u1z * v1z + u2z * v2z + u3z * v3z;
}

// ---------------- fused kernel: bulk-copy pipeline + reduce + tail ----------
__global__ __launch_bounds__(288, 7) void fused256_kernel(const float* __restrict__ x,
                                                          const float* __restrict__ W,
                                                          float* __restrict__ out,
                                                          int Btot) {
    __shared__ __align__(16) float stg[3][2304];            // 3-stage ring, 9216B each
    __shared__ __align__(8) unsigned long long full_[3], empty_[3];
    __shared__ float cam[16 * 9];                           // per-block camera matrices
    const int t    = threadIdx.x;     // 0..287
    const int lane = t & 31;
    const int w    = t >> 5;          // warp id 0..8 == output slot j
    const int step = gridDim.x;

    if (t == 0) {
#pragma unroll
        for (int s = 0; s < 3; ++s) {
            mbar_init(smem_u32(&full_[s]), 1);    // tx-based completion
            mbar_init(smem_u32(&empty_[s]), 9);   // one arrive per consumer warp
        }
    }
    float wreg[8];
#pragma unroll
    for (int k = 0; k < 8; ++k) wreg[k] = W[lane + 32 * k];
    __syncthreads();   // mbarriers visible CTA-wide before any TMA/arrive

    if (t == 0) {      // prologue: fill all 3 stages
#pragma unroll
        for (int p = 0; p < 3; ++p) {
            int bp = blockIdx.x + p * step;
            if (bp < Btot) {
                mbar_expect_tx(smem_u32(&full_[p]), 9216u);
                bulk_g2s(smem_u32(stg[p]), x + (size_t)bp * 2304, 9216u,
                         smem_u32(&full_[p]));
            }
        }
    }

    int b  = blockIdx.x;
    int it = 0;
    for (int k = 0; ; ++k) {
        if (b >= Btot) break;
        const int      s  = k - (k / 3) * 3;          // k % 3
        const unsigned ph = (unsigned)((k / 3) & 1);  // phase parity of this round

        mbar_wait(smem_u32(&full_[s]), ph);           // data arrived (acquire)

        const float* sf = stg[s];
        float sum = 0.f;
#pragma unroll
        for (int q = 0; q < 8; ++q)
            sum += sf[(lane + 32 * q) * 9 + w] * wreg[q];   // stride 9: conflict-free
#pragma unroll
        for (int off = 16; off > 0; off >>= 1)
            sum += __shfl_xor_sync(0xffffffffu, sum, off);  // warp-synchronizing

        if (lane == 0) {
            cam[k * 9 + w] = sum;
            mbar_arrive(smem_u32(&empty_[s]));        // warp done reading stage s
        }

        if (t == 0) {                                 // producer: refill stage s
            int bn = b + 3 * step;
            if (bn < Btot) {
                mbar_wait(smem_u32(&empty_[s]), ph);  // all 9 warps released it
                mbar_expect_tx(smem_u32(&full_[s]), 9216u);
                bulk_g2s(smem_u32(stg[s]), x + (size_t)bn * 2304, 9216u,
                         smem_u32(&full_[s]));
            }
        }
        b += step;
        it = k;
    }
    __syncthreads();

    // tail: first (it+1) threads each solve one 3x3 problem
    if (t <= it) {
        float o[9];
        solve3x3(cam + t * 9, o);
        float* op = out + ((size_t)blockIdx.x + (size_t)step * t) * 9;
#pragma unroll
        for (int j = 0; j < 9; ++j) op[j] = o[j];
    }
}

// ---------------- fallback path (unexpected shapes) -------------------------
__global__ void reduce_generic(const float* __restrict__ x, const float* __restrict__ W,
                               int B, int C) {
    int b = blockIdx.x * blockDim.x + threadIdx.x;
    if (b >= B) return;
    float acc[9];
#pragma unroll
    for (int j = 0; j < 9; ++j) acc[j] = 0.f;
    const float* p = x + (size_t)b * C * 9;
    for (int c = 0; c < C; ++c) {
        float wv = W[c];
#pragma unroll
        for (int j = 0; j < 9; ++j) acc[j] += p[c * 9 + j] * wv;
    }
#pragma unroll
    for (int j = 0; j < 9; ++j) g_cam[(size_t)b * 9 + j] = acc[j];
}

__global__ __launch_bounds__(128) void solve_kernel(float* __restrict__ out, int Btot) {
    int b = blockIdx.x * blockDim.x + threadIdx.x;
    if (b >= Btot) return;
    float mm[9];
#pragma unroll
    for (int j = 0; j < 9; ++j) mm[j] = g_cam[(size_t)b * 9 + j];
    float o[9];
    solve3x3(mm, o);
#pragma unroll
    for (int j = 0; j < 9; ++j) out[(size_t)b * 9 + j] = o[j];
}

// ---------------------------------------------------------------------------
extern "C" void kernel_launch(void* const* d_in, const int* in_sizes, int n_in,
                              void* d_out, int out_size) {
    const float* x = (const float*)d_in[0];
    const float* W = (const float*)d_in[1];
    float* out = (float*)d_out;

    int C = in_sizes[1];
    int B = in_sizes[0] / (C * 9);

    if (C == 256 && B <= 32 * 1024) {
        int grid = B < 2048 ? B : 2048;   // <= 16 tiles per block
        fused256_kernel<<<grid, 288>>>(x, W, out, B);
    } else {
        if (B > MAXB) B = MAXB;
        reduce_generic<<<(B + 127) / 128, 128>>>(x, W, B, C);
        solve_kernel<<<(B + 127) / 128, 128>>>(out, B);
    }
}

// round 14
// speedup vs baseline: 1.1624x; 1.1624x over previous
#include <cuda_runtime.h>
#include <math.h>

// ---------------------------------------------------------------------------
// CameraEstimator: camera[b] = sum_c x[b,c,:,:] * W[c]  (B=32768, C=256)
// then R[b] = nearest special-orthogonal matrix to camera[b].
//
// Fused single kernel: grid=2048 blocks, each streams 16 b-tiles through a
// 3-stage SMEM ring filled by cp.async.cg (all 288 threads issue; no STS leg,
// no register prefetch). One __syncthreads per tile; prefetch depth 2.
// 9 warps -> 9 outputs via conflict-free stride-9 LDS + shuffle reduce;
// 16-thread tail solves the 3x3 Procrustes problems.
//
// R = u1 v1^T + u2 v2^T + (u1 x u2)(v1 x v2)^T with v1,v2 top eigenvectors
// of M^T M, u_i = GS-normalized M v_i == reference u_flip @ vh.
// ---------------------------------------------------------------------------

#define MAXB 65536
__device__ float g_cam[MAXB * 9];   // fallback path only

static __device__ __forceinline__ unsigned smem_u32(const void* p) {
    unsigned a;
    asm("{ .reg .u64 t; cvta.to.shared.u64 t, %1; cvt.u32.u64 %0, t; }"
        : "=r"(a) : "l"(p));
    return a;
}
static __device__ __forceinline__ void cp16(unsigned dst, const void* src) {
    asm volatile("cp.async.cg.shared.global [%0], [%1], 16;"
                 :: "r"(dst), "l"(src) : "memory");
}
static __device__ __forceinline__ void cp_commit() {
    asm volatile("cp.async.commit_group;" ::: "memory");
}
template <int N>
static __device__ __forceinline__ void cp_wait() {
    asm volatile("cp.async.wait_group %0;" :: "n"(N) : "memory");
}

// ---------------- shared 3x3 Procrustes solve (fp32) ------------------------

__device__ __forceinline__ void bestNull(float a00, float a01, float a02,
                                         float a11, float a12, float a22,
                                         float lam, float& vx, float& vy, float& vz) {
    float b00 = a00 - lam, b11 = a11 - lam, b22 = a22 - lam;
    float c0x = a01 * a12 - a02 * b11;      // r0 x r1
    float c0y = a02 * a01 - b00 * a12;
    float c0z = b00 * b11 - a01 * a01;
    float c1x = a01 * b22 - a02 * a12;      // r0 x r2
    float c1y = a02 * a02 - b00 * b22;
    float c1z = b00 * a12 - a01 * a02;
    float c2x = b11 * b22 - a12 * a12;      // r1 x r2
    float c2y = a12 * a02 - a01 * b22;
    float c2z = a01 * a12 - b11 * a02;
    float n0 = c0x * c0x + c0y * c0y + c0z * c0z;
    float n1 = c1x * c1x + c1y * c1y + c1z * c1z;
    float n2 = c2x * c2x + c2y * c2y + c2z * c2z;
    float nx = c0x, ny = c0y, nz = c0z, nn = n0;
    if (n1 > nn) { nx = c1x; ny = c1y; nz = c1z; nn = n1; }
    if (n2 > nn) { nx = c2x; ny = c2y; nz = c2z; nn = n2; }
    if (nn < 1e-30f) { vx = 1.f; vy = 0.f; vz = 0.f; return; }
    float r = rsqrtf(nn);
    vx = nx * r; vy = ny * r; vz = nz * r;
}

__device__ __forceinline__ void perpOf(float vx, float vy, float vz,
                                       float& px, float& py, float& pz) {
    float ax = fabsf(vx), ay = fabsf(vy), az = fabsf(vz);
    float ex = 0.f, ey = 0.f, ez = 0.f;
    if (ax <= ay && ax <= az) ex = 1.f;
    else if (ay <= az)        ey = 1.f;
    else                      ez = 1.f;
    px = ey * vz - ez * vy;
    py = ez * vx - ex * vz;
    pz = ex * vy - ey * vx;
}

__device__ __forceinline__ void solve3x3(const float* __restrict__ m,
                                         float* __restrict__ o) {
    float m00 = m[0], m01 = m[1], m02 = m[2];
    float m10 = m[3], m11 = m[4], m12 = m[5];
    float m20 = m[6], m21 = m[7], m22 = m[8];

    float a00 = m00 * m00 + m10 * m10 + m20 * m20;
    float a01 = m00 * m01 + m10 * m11 + m20 * m21;
    float a02 = m00 * m02 + m10 * m12 + m20 * m22;
    float a11 = m01 * m01 + m11 * m11 + m21 * m21;
    float a12 = m01 * m02 + m11 * m12 + m21 * m22;
    float a22 = m02 * m02 + m12 * m12 + m22 * m22;

    float tr  = a00 + a11 + a22;
    float inv = (tr > 1e-30f) ? (1.0f / tr) : 0.f;
    a00 *= inv; a01 *= inv; a02 *= inv;
    a11 *= inv; a12 *= inv; a22 *= inv;

    float e2 = a00 * a11 + a00 * a22 + a11 * a22
             - a01 * a01 - a02 * a02 - a12 * a12;
    float dm = m00 * (m11 * m22 - m12 * m21)
             - m01 * (m10 * m22 - m12 * m20)
             + m02 * (m10 * m21 - m11 * m20);
    float e3 = (dm * dm) * (inv * inv * inv);

    float p2  = 1.0f - 3.0f * e2; if (p2 < 0.f) p2 = 0.f;
    float lam = (1.0f / 3.0f) + (2.0f / 3.0f) * sqrtf(p2);
#pragma unroll
    for (int it = 0; it < 8; ++it) {
        float f  = ((lam - 1.0f) * lam + e2) * lam - e3;
        float fp = (3.0f * lam - 2.0f) * lam + e2;
        lam -= f / (fp + 1e-30f);
    }
    float S = 1.0f - lam;
    float P = e2 - lam * S;
    float disc = S * S - 4.0f * P; if (disc < 0.f) disc = 0.f;
    float L2 = 0.5f * (S + sqrtf(disc));

    float v1x, v1y, v1z;
    bestNull(a00, a01, a02, a11, a12, a22, lam, v1x, v1y, v1z);

    float c2x, c2y, c2z;
    bestNull(a00, a01, a02, a11, a12, a22, L2, c2x, c2y, c2z);
    float dp = c2x * v1x + c2y * v1y + c2z * v1z;
    float v2x = c2x - dp * v1x, v2y = c2y - dp * v1y, v2z = c2z - dp * v1z;
    float n = v2x * v2x + v2y * v2y + v2z * v2z;
    if (n < 1e-12f) { perpOf(v1x, v1y, v1z, v2x, v2y, v2z);
                      n = v2x * v2x + v2y * v2y + v2z * v2z; }
    float rn = rsqrtf(n);
    v2x *= rn; v2y *= rn; v2z *= rn;
    float v3x = v1y * v2z - v1z * v2y;
    float v3y = v1z * v2x - v1x * v2z;
    float v3z = v1x * v2y - v1y * v2x;

    float u1x = m00 * v1x + m01 * v1y + m02 * v1z;
    float u1y = m10 * v1x + m11 * v1y + m12 * v1z;
    float u1z = m20 * v1x + m21 * v1y + m22 * v1z;
    n = u1x * u1x + u1y * u1y + u1z * u1z;
    if (n < 1e-30f) { u1x = 1.f; u1y = 0.f; u1z = 0.f; n = 1.f; }
    rn = rsqrtf(n); u1x *= rn; u1y *= rn; u1z *= rn;

    float t2x = m00 * v2x + m01 * v2y + m02 * v2z;
    float t2y = m10 * v2x + m11 * v2y + m12 * v2z;
    float t2z = m20 * v2x + m21 * v2y + m22 * v2z;
    dp = t2x * u1x + t2y * u1y + t2z * u1z;
    t2x -= dp * u1x; t2y -= dp * u1y; t2z -= dp * u1z;
    n = t2x * t2x + t2y * t2y + t2z * t2z;
    if (n < 1e-20f) { perpOf(u1x, u1y, u1z, t2x, t2y, t2z);
                      n = t2x * t2x + t2y * t2y + t2z * t2z; }
    rn = rsqrtf(n);
    float u2x = t2x * rn, u2y = t2y * rn, u2z = t2z * rn;
    float u3x = u1y * u2z - u1z * u2y;
    float u3y = u1z * u2x - u1x * u2z;
    float u3z = u1x * u2y - u1y * u2x;

    o[0] = u1x * v1x + u2x * v2x + u3x * v3x;
    o[1] = u1x * v1y + u2x * v2y + u3x * v3y;
    o[2] = u1x * v1z + u2x * v2z + u3x * v3z;
    o[3] = u1y * v1x + u2y * v2x + u3y * v3x;
    o[4] = u1y * v1y + u2y * v2y + u3y * v3y;
    o[5] = u1y * v1z + u2y * v2z + u3y * v3z;
    o[6] = u1z * v1x + u2z * v2x + u3z * v3x;
    o[7] = u1z * v1y + u2z * v2y + u3z * v3y;
    o[8] = u1z * v1z + u2z * v2z + u3z * v3z;
}

// ---------------- fused kernel: cp.async ring + reduce + tail ---------------
__global__ __launch_bounds__(288, 7) void fused256_kernel(const float* __restrict__ x,
                                                          const float* __restrict__ W,
                                                          float* __restrict__ out,
                                                          int Btot) {
    __shared__ __align__(16) float stg[3][2304];   // 3-stage ring, 9216B/stage
    __shared__ float cam[16 * 9];                  // per-block camera matrices
    const int t    = threadIdx.x;     // 0..287
    const int lane = t & 31;
    const int w    = t >> 5;          // warp id 0..8 == output slot j
    const int step = gridDim.x;

    float wreg[8];
#pragma unroll
    for (int k = 0; k < 8; ++k) wreg[k] = W[lane + 32 * k];

    const unsigned d0 = smem_u32(&stg[0][0]) + (unsigned)t * 16u;
    const unsigned d1 = d0 + 288u * 16u;
    const unsigned stgB = 9216u;

    // prologue: prefetch tiles 0,1 (one commit group each; empty groups OK)
#pragma unroll
    for (int p = 0; p < 2; ++p) {
        int bp = blockIdx.x + p * step;
        if (bp < Btot) {
            const char* src = (const char*)(x + (size_t)bp * 2304) + (size_t)t * 16;
            cp16(d0 + p * stgB, src);
            cp16(d1 + p * stgB, src + 288 * 16);
        }
        cp_commit();
    }

    int b  = blockIdx.x;
    int it = 0;
    for (int k = 0; ; ++k) {
        if (b >= Btot) break;
        const int s = k - (k / 3) * 3;            // k % 3

        cp_wait<1>();          // my chunks of tile k have landed (FIFO groups)
        __syncthreads();       // publish everyone's chunks; seal compute(k-1)

        {   // prefetch tile k+2 into stage (k+2)%3 (held tile k-1, now sealed)
            int bn = b + 2 * step;
            const int sp = (s + 2 >= 3) ? s - 1 : s + 2;   // (k+2)%3
            if (bn < Btot) {
                const char* src = (const char*)(x + (size_t)bn * 2304) + (size_t)t * 16;
                cp16(d0 + sp * stgB, src);
                cp16(d1 + sp * stgB, src + 288 * 16);
            }
            cp_commit();       // always commit to keep group indexing aligned
        }

        const float* sf = stg[s];
        float sum = 0.f;
#pragma unroll
        for (int q = 0; q < 8; ++q)
            sum += sf[(lane + 32 * q) * 9 + w] * wreg[q];   // stride 9: conflict-free
#pragma unroll
        for (int off = 16; off > 0; off >>= 1)
            sum += __shfl_xor_sync(0xffffffffu, sum, off);
        if (lane == 0) cam[k * 9 + w] = sum;

        b += step;
        it = k;
    }
    __syncthreads();

    // tail: first (it+1) threads each solve one 3x3 problem
    if (t <= it) {
        float o[9];
        solve3x3(cam + t * 9, o);
        float* op = out + ((size_t)blockIdx.x + (size_t)step * t) * 9;
#pragma unroll
        for (int j = 0; j < 9; ++j) op[j] = o[j];
    }
}

// ---------------- fallback path (unexpected shapes) -------------------------
__global__ void reduce_generic(const float* __restrict__ x, const float* __restrict__ W,
                               int B, int C) {
    int b = blockIdx.x * blockDim.x + threadIdx.x;
    if (b >= B) return;
    float acc[9];
#pragma unroll
    for (int j = 0; j < 9; ++j) acc[j] = 0.f;
    const float* p = x + (size_t)b * C * 9;
    for (int c = 0; c < C; ++c) {
        float wv = W[c];
#pragma unroll
        for (int j = 0; j < 9; ++j) acc[j] += p[c * 9 + j] * wv;
    }
#pragma unroll
    for (int j = 0; j < 9; ++j) g_cam[(size_t)b * 9 + j] = acc[j];
}

__global__ __launch_bounds__(128) void solve_kernel(float* __restrict__ out, int Btot) {
    int b = blockIdx.x * blockDim.x + threadIdx.x;
    if (b >= Btot) return;
    float mm[9];
#pragma unroll
    for (int j = 0; j < 9; ++j) mm[j] = g_cam[(size_t)b * 9 + j];
    float o[9];
    solve3x3(mm, o);
#pragma unroll
    for (int j = 0; j < 9; ++j) out[(size_t)b * 9 + j] = o[j];
}

// ---------------------------------------------------------------------------
extern "C" void kernel_launch(void* const* d_in, const int* in_sizes, int n_in,
                              void* d_out, int out_size) {
    const float* x = (const float*)d_in[0];
    const float* W = (const float*)d_in[1];
    float* out = (float*)d_out;

    int C = in_sizes[1];
    int B = in_sizes[0] / (C * 9);

    if (C == 256 && B <= 32 * 1024) {
        int grid = B < 2048 ? B : 2048;   // <= 16 tiles per block
        fused256_kernel<<<grid, 288>>>(x, W, out, B);
    } else {
        if (B > MAXB) B = MAXB;
        reduce_generic<<<(B + 127) / 128, 128>>>(x, W, B, C);
        solve_kernel<<<(B + 127) / 128, 128>>>(out, B);
    }
}